// round 16
// baseline (speedup 1.0000x reference)
#include <cuda_runtime.h>
#include <cuda_bf16.h>
#include <math.h>
#include <stdint.h>

#define BB   128
#define SS   512
#define HH   1024
#define FEAT 576
#define EE   512
#define XEE  64
#define BH   (BB*HH)
#define NB   129
#define K1A  1600
#define K2A  2048
#define NG   4096
#define SK   40                          // smem row stride (bf16 elems)
#define SMEM_DYN (4*128*SK*2)            // Ahi,Alo,Whi,Wlo = 40960 B

// ---------------- device scratch ----------------
__device__ __align__(128) float g_X[(size_t)SS*BB*FEAT];
__device__ __align__(128) float g_W1[(size_t)NG*K1A];
__device__ __align__(128) float g_W2[(size_t)NG*K2A];
__device__ __align__(128) float g_cat1[BB*K1A];
__device__ __align__(128) float g_cat2[BB*K2A];
__device__ __align__(128) float g_h1[BH], g_c1[BH], g_h2[BH], g_c2[BH];
__device__ __align__(128) float g_ppa[8][BH], g_ppb[8][BH];
__device__ __align__(128) float g_pz[4][BB*NG];
__device__ __align__(128) float g_s[BB];
__device__ float g_flag;
__device__ __align__(128) float g_wx[FEAT], g_wh[HH];
__device__ float g_c0;
__device__ unsigned g_arrive;

__device__ __forceinline__ float sigm(float x) { return 1.0f/(1.0f + expf(-x)); }

__device__ __forceinline__ void mma_bf16(float (&d)[4], const uint32_t (&a)[4],
                                         const uint32_t (&b)[2])
{
    asm volatile(
        "mma.sync.aligned.m16n8k16.row.col.f32.bf16.bf16.f32 "
        "{%0,%1,%2,%3}, {%4,%5,%6,%7}, {%8,%9}, {%0,%1,%2,%3};"
        : "+f"(d[0]), "+f"(d[1]), "+f"(d[2]), "+f"(d[3])
        : "r"(a[0]), "r"(a[1]), "r"(a[2]), "r"(a[3]), "r"(b[0]), "r"(b[1]));
}

// pack 4 fp32 -> (hi uint2, lo uint2) of bf16 pairs
__device__ __forceinline__ void split4(float4 v, uint2 &hi, uint2 &lo)
{
    __nv_bfloat16 hx = __float2bfloat16_rn(v.x);
    __nv_bfloat16 hy = __float2bfloat16_rn(v.y);
    __nv_bfloat16 hz = __float2bfloat16_rn(v.z);
    __nv_bfloat16 hw = __float2bfloat16_rn(v.w);
    __nv_bfloat16 lx = __float2bfloat16_rn(v.x - __bfloat162float(hx));
    __nv_bfloat16 ly = __float2bfloat16_rn(v.y - __bfloat162float(hy));
    __nv_bfloat16 lz = __float2bfloat16_rn(v.z - __bfloat162float(hz));
    __nv_bfloat16 lw = __float2bfloat16_rn(v.w - __bfloat162float(hw));
    __nv_bfloat162 h01 = __nv_bfloat162(hx, hy), h23 = __nv_bfloat162(hz, hw);
    __nv_bfloat162 l01 = __nv_bfloat162(lx, ly), l23 = __nv_bfloat162(lz, lw);
    hi.x = *reinterpret_cast<uint32_t*>(&h01); hi.y = *reinterpret_cast<uint32_t*>(&h23);
    lo.x = *reinterpret_cast<uint32_t*>(&l01); lo.y = *reinterpret_cast<uint32_t*>(&l23);
}

__device__ __forceinline__ void grid_sync(unsigned &gen)
{
    __syncthreads();
    __threadfence();
    gen += NB;
    if (threadIdx.x == 0) {
        atomicAdd(&g_arrive, 1u);
        while (*(volatile unsigned*)&g_arrive < gen) { __nanosleep(64); }
    }
    __syncthreads();
    __threadfence();
}

// ---------------- prep kernels ----------------
__global__ void prep_kernel(const float* __restrict__ Wsi, const float* __restrict__ Wsh,
                            const float* __restrict__ b_bd, const float* __restrict__ vs)
{
    int idx = blockIdx.x*256 + threadIdx.x;
    if (idx < FEAT) {
        float s = 0.f;
        for (int j = 0; j < 512; ++j) s += Wsi[(size_t)j*FEAT + idx]*vs[j];
        g_wx[idx] = s;
    } else if (idx < FEAT + HH) {
        int h = idx - FEAT;
        float s = 0.f;
        for (int j = 0; j < 512; ++j) s += Wsh[(size_t)j*HH + h]*vs[j];
        g_wh[h] = s;
    } else if (idx == FEAT + HH) {
        float s = 0.f;
        for (int j = 0; j < 512; ++j) s += b_bd[j]*vs[j];
        g_c0 = s;
    }
}

__global__ void prep2_kernel(const float* __restrict__ Wih1, const float* __restrict__ Whh1,
                             const float* __restrict__ Wih2, const float* __restrict__ Whh2)
{
    size_t n1 = (size_t)NG*K1A, n2 = (size_t)NG*K2A;
    for (size_t i = (size_t)blockIdx.x*blockDim.x + threadIdx.x; i < n1 + n2;
         i += (size_t)gridDim.x*blockDim.x) {
        if (i < n1) {
            int n = (int)(i / K1A), k = (int)(i % K1A);
            g_W1[i] = (k < FEAT) ? Wih1[(size_t)n*FEAT + k] : Whh1[(size_t)n*HH + (k-FEAT)];
        } else {
            size_t j = i - n1;
            int n = (int)(j / K2A), k = (int)(j % K2A);
            g_W2[j] = (k < HH) ? Wih2[(size_t)n*HH + k] : Whh2[(size_t)n*HH + (k-HH)];
        }
    }
}

__global__ void zero_kernel()
{
    int i = blockIdx.x*256 + threadIdx.x;
    g_h1[i] = 0.f; g_c1[i] = 0.f; g_h2[i] = 0.f; g_c2[i] = 0.f;
    if (i == 0) g_arrive = 0u;
}

__global__ void gather_kernel(const int* __restrict__ enc, const int* __restrict__ encx,
                              const float* __restrict__ wemb, const float* __restrict__ xemb)
{
    size_t total = (size_t)SS*BB*FEAT;
    for (size_t i = (size_t)blockIdx.x*blockDim.x + threadIdx.x; i < total;
         i += (size_t)gridDim.x*blockDim.x) {
        int f  = (int)(i % FEAT);
        size_t tb = i / FEAT;
        int b = (int)(tb % BB);
        int t = (int)(tb / BB);
        float v;
        if (f < EE) v = wemb[(size_t)enc [(size_t)b*SS + t]*EE  + f];
        else        v = xemb[(size_t)encx[(size_t)b*SS + t]*XEE + (f - EE)];
        g_X[i] = v;
    }
}

// ---------------- tensor-core GEMM via mma.sync (bf16 x3 split) --------------
// C[128,128] = A[128,Kr] @ W[128 rows,Kr]^T.  256 threads = 8 warps (4m x 2n),
// warp tile 32x64 (2 x 8 m16n8k16 fragments, 3 MMAs each for the error split).
// K-chunks of 32 fp32 elems = 2 k16 MMA steps. Row stride SK=40 bf16:
// fragment uint32 loads hit 32 distinct banks.
__device__ void tc_gemm(const float* __restrict__ A, int lda,
                        const float* __restrict__ W, int ldw,
                        float* __restrict__ C, int ldc,
                        int kbeg, int nch, __nv_bfloat16* __restrict__ sm)
{
    __nv_bfloat16* Ahi = sm;
    __nv_bfloat16* Alo = sm + 128*SK;
    __nv_bfloat16* Whi = sm + 2*128*SK;
    __nv_bfloat16* Wlo = sm + 3*128*SK;
    const int tid = threadIdx.x;
    const int warp = tid >> 5, lane = tid & 31;
    const int wm = (warp & 3) * 32, wn = (warp >> 2) * 64;
    const int grp = lane >> 2, tig = lane & 3;
    const int lrow = tid >> 3, lkc = (tid & 7) * 4;      // staging: rows 0..31 (+32r), k quad

    float acc[2][8][4];
    #pragma unroll
    for (int mi = 0; mi < 2; ++mi)
        #pragma unroll
        for (int ni = 0; ni < 8; ++ni)
            #pragma unroll
            for (int q = 0; q < 4; ++q) acc[mi][ni][q] = 0.f;

    const float* Ap = A + (size_t)lrow*lda + kbeg + lkc;
    const float* Wp = W + (size_t)lrow*ldw + kbeg + lkc;
    float4 ra[4], rw[4];
    #pragma unroll
    for (int r = 0; r < 4; ++r) {
        ra[r] = *(const float4*)(Ap + (size_t)(32*r)*lda);
        rw[r] = *(const float4*)(Wp + (size_t)(32*r)*ldw);
    }

    for (int c = 0; c < nch; ++c) {
        __syncthreads();
        #pragma unroll
        for (int r = 0; r < 4; ++r) {
            int row = lrow + 32*r;
            uint2 hi, lo;
            split4(ra[r], hi, lo);
            *(uint2*)(Ahi + row*SK + lkc) = hi;
            *(uint2*)(Alo + row*SK + lkc) = lo;
            split4(rw[r], hi, lo);
            *(uint2*)(Whi + row*SK + lkc) = hi;
            *(uint2*)(Wlo + row*SK + lkc) = lo;
        }
        __syncthreads();
        if (c + 1 < nch) {
            #pragma unroll
            for (int r = 0; r < 4; ++r) {
                ra[r] = *(const float4*)(Ap + (size_t)(32*r)*lda + (c + 1)*32);
                rw[r] = *(const float4*)(Wp + (size_t)(32*r)*ldw + (c + 1)*32);
            }
        }
        #pragma unroll
        for (int k16 = 0; k16 < 2; ++k16) {
            const int kof = k16*16 + 2*tig;
            uint32_t ah[2][4], al[2][4];
            #pragma unroll
            for (int mi = 0; mi < 2; ++mi) {
                int r0 = wm + mi*16 + grp;
                int b0 = r0*SK + kof, b1 = (r0+8)*SK + kof;
                ah[mi][0] = *(const uint32_t*)(Ahi + b0);
                ah[mi][1] = *(const uint32_t*)(Ahi + b1);
                ah[mi][2] = *(const uint32_t*)(Ahi + b0 + 8);
                ah[mi][3] = *(const uint32_t*)(Ahi + b1 + 8);
                al[mi][0] = *(const uint32_t*)(Alo + b0);
                al[mi][1] = *(const uint32_t*)(Alo + b1);
                al[mi][2] = *(const uint32_t*)(Alo + b0 + 8);
                al[mi][3] = *(const uint32_t*)(Alo + b1 + 8);
            }
            #pragma unroll
            for (int ni = 0; ni < 8; ++ni) {
                int wb = (wn + ni*8 + grp)*SK + kof;
                uint32_t wh[2] = { *(const uint32_t*)(Whi + wb),
                                   *(const uint32_t*)(Whi + wb + 8) };
                uint32_t wl[2] = { *(const uint32_t*)(Wlo + wb),
                                   *(const uint32_t*)(Wlo + wb + 8) };
                #pragma unroll
                for (int mi = 0; mi < 2; ++mi) {
                    mma_bf16(acc[mi][ni], ah[mi], wh);
                    mma_bf16(acc[mi][ni], al[mi], wh);
                    mma_bf16(acc[mi][ni], ah[mi], wl);
                }
            }
        }
    }
    #pragma unroll
    for (int mi = 0; mi < 2; ++mi)
        #pragma unroll
        for (int ni = 0; ni < 8; ++ni) {
            int row = wm + mi*16 + grp;
            int col = wn + ni*8 + 2*tig;
            *(float2*)(C + (size_t)row*ldc + col)     = make_float2(acc[mi][ni][0], acc[mi][ni][1]);
            *(float2*)(C + (size_t)(row+8)*ldc + col) = make_float2(acc[mi][ni][2], acc[mi][ni][3]);
        }
}

// ---------------- persistent main kernel ----------------
__global__ void __launch_bounds__(256)
main_kernel(const float* __restrict__ Wmx1, const float* __restrict__ Wmh1,
            const float* __restrict__ b1,
            const float* __restrict__ Wmx2, const float* __restrict__ Wmh2,
            const float* __restrict__ b2,
            float* __restrict__ out, float* __restrict__ flags_out)
{
    extern __shared__ __nv_bfloat16 smb[];
    const int tid = threadIdx.x, blk = blockIdx.x;
    unsigned gen = 0;

    for (int t = 0; t < SS; ++t) {
        const float* Xt = g_X + (size_t)t*BB*FEAT;

        // ---- P1: m1 partials + boundary detector ----
        if (blk == 128) {
            int w = tid >> 5, lane = tid & 31;
            for (int b = w; b < BB; b += 8) {
                float sum = 0.f;
                for (int k = lane; k < FEAT; k += 32) sum += Xt[(size_t)b*FEAT + k]*g_wx[k];
                for (int k = lane; k < HH;   k += 32) sum += g_h1[(size_t)b*HH + k]*g_wh[k];
                #pragma unroll
                for (int off = 16; off > 0; off >>= 1)
                    sum += __shfl_xor_sync(0xFFFFFFFFu, sum, off);
                if (lane == 0) {
                    float s = (sum + g_c0 > 0.f) ? 1.f : 0.f;
                    g_s[b] = s;
                    if (b == 0) { g_flag = s; flags_out[t] = s; }
                }
            }
        } else if (blk < 32) {                 // pa: x@Wmx1^T, K=576, 4 splits {5,5,4,4}ch
            int nt = blk >> 2, sp = blk & 3;
            int kbeg = (sp < 2) ? sp*160 : 320 + (sp-2)*128;
            int nch  = 5 - (sp >> 1);
            tc_gemm(Xt, FEAT, Wmx1 + (size_t)(nt*128)*FEAT, FEAT,
                    g_ppa[sp] + nt*128, HH, kbeg, nch, smb);
        } else if (blk < 96) {                 // pb: h1@Wmh1^T, K=1024, 8 splits x4ch
            int q = blk - 32, nt = q >> 3, sp = q & 7;
            tc_gemm(g_h1, HH, Wmh1 + (size_t)(nt*128)*HH, HH,
                    g_ppb[sp] + nt*128, HH, sp*128, 4, smb);
        }
        grid_sync(gen);

        // ---- P2: m1 -> cat1[:,576:]; Xt -> cat1[:,:576] ----
        for (int i = blk*256 + tid; i < BH/4; i += NB*256) {
            int m = i >> 8, c4 = (i & 255) * 4;
            float4 a = make_float4(0,0,0,0), b = make_float4(0,0,0,0);
            #pragma unroll
            for (int s = 0; s < 4; ++s) {
                float4 pa = *(const float4*)(g_ppa[s] + (size_t)m*HH + c4);
                a.x += pa.x; a.y += pa.y; a.z += pa.z; a.w += pa.w;
            }
            #pragma unroll
            for (int s = 0; s < 8; ++s) {
                float4 pb = *(const float4*)(g_ppb[s] + (size_t)m*HH + c4);
                b.x += pb.x; b.y += pb.y; b.z += pb.z; b.w += pb.w;
            }
            *(float4*)(g_cat1 + (size_t)m*K1A + FEAT + c4) =
                make_float4(a.x*b.x, a.y*b.y, a.z*b.z, a.w*b.w);
        }
        for (int i = blk*256 + tid; i < BB*FEAT/4; i += NB*256) {
            int m = i / 144, c4 = (i % 144) * 4;
            *(float4*)(g_cat1 + (size_t)m*K1A + c4) = *(const float4*)(Xt + (size_t)m*FEAT + c4);
        }
        grid_sync(gen);

        // ---- P3: z1 partials: cat1 @ W1^T, K=1600, 32nt x 4sp {13,13,12,12}ch ----
        if (blk < 128) {
            int nt = blk >> 2, sp = blk & 3;
            int kbeg = (sp < 2) ? sp*416 : 832 + (sp-2)*384;
            int nch  = 13 - (sp >> 1);
            tc_gemm(g_cat1, K1A, g_W1 + (size_t)(nt*128)*K1A, K1A,
                    g_pz[sp] + nt*128, NG, kbeg, nch, smb);
        }
        grid_sync(gen);

        bool flag = (*(volatile float*)&g_flag > 0.5f);

        // ---- P3b: gates 1 epilogue ----
        for (int i = blk*256 + tid; i < BH/4; i += NB*256) {
            int m = i >> 8, c4 = (i & 255) * 4;
            float4 z[4];
            #pragma unroll
            for (int g = 0; g < 4; ++g) {
                int col = g*HH + c4;
                float4 sum = *(const float4*)(b1 + col);
                #pragma unroll
                for (int s = 0; s < 4; ++s) {
                    float4 p = *(const float4*)(g_pz[s] + (size_t)m*NG + col);
                    sum.x += p.x; sum.y += p.y; sum.z += p.z; sum.w += p.w;
                }
                z[g] = sum;
            }
            float s = g_s[m];
            size_t idx = (size_t)m*HH + c4;
            float4 co = *(const float4*)(g_c1 + idx);
            float cn0 = sigm(z[1].x)*co.x + sigm(z[0].x)*tanhf(z[2].x);
            float cn1 = sigm(z[1].y)*co.y + sigm(z[0].y)*tanhf(z[2].y);
            float cn2 = sigm(z[1].z)*co.z + sigm(z[0].z)*tanhf(z[2].z);
            float cn3 = sigm(z[1].w)*co.w + sigm(z[0].w)*tanhf(z[2].w);
            float hn0 = sigm(z[3].x)*tanhf(cn0);
            float hn1 = sigm(z[3].y)*tanhf(cn1);
            float hn2 = sigm(z[3].z)*tanhf(cn2);
            float hn3 = sigm(z[3].w)*tanhf(cn3);
            *(float4*)(g_cat2 + (size_t)m*K2A + c4) = make_float4(hn0*s, hn1*s, hn2*s, hn3*s);
            float r = 1.f - s;
            *(float4*)(g_h1 + idx) = make_float4(hn0*r, hn1*r, hn2*r, hn3*r);
            *(float4*)(g_c1 + idx) = make_float4(cn0*r, cn1*r, cn2*r, cn3*r);
            if (!flag)
                *(float4*)(out + ((size_t)m*SS + t)*HH + c4) = *(const float4*)(g_h2 + idx);
        }
        grid_sync(gen);

        if (flag) {
            // ---- P4: m2 partials, K=1024, 8nt x 8sp each side ----
            if (blk < 64) {
                int nt = blk >> 3, sp = blk & 7;
                tc_gemm(g_cat2, K2A, Wmx2 + (size_t)(nt*128)*HH, HH,
                        g_ppa[sp] + nt*128, HH, sp*128, 4, smb);
            } else if (blk < 128) {
                int q = blk - 64, nt = q >> 3, sp = q & 7;
                tc_gemm(g_h2, HH, Wmh2 + (size_t)(nt*128)*HH, HH,
                        g_ppb[sp] + nt*128, HH, sp*128, 4, smb);
            }
            grid_sync(gen);

            // ---- P5: m2 -> cat2[:,1024:] ----
            for (int i = blk*256 + tid; i < BH/4; i += NB*256) {
                int m = i >> 8, c4 = (i & 255) * 4;
                float4 a = make_float4(0,0,0,0), b = make_float4(0,0,0,0);
                #pragma unroll
                for (int s = 0; s < 8; ++s) {
                    float4 pa = *(const float4*)(g_ppa[s] + (size_t)m*HH + c4);
                    float4 pb = *(const float4*)(g_ppb[s] + (size_t)m*HH + c4);
                    a.x += pa.x; a.y += pa.y; a.z += pa.z; a.w += pa.w;
                    b.x += pb.x; b.y += pb.y; b.z += pb.z; b.w += pb.w;
                }
                *(float4*)(g_cat2 + (size_t)m*K2A + HH + c4) =
                    make_float4(a.x*b.x, a.y*b.y, a.z*b.z, a.w*b.w);
            }
            grid_sync(gen);

            // ---- P6: z2 partials: cat2 @ W2^T, K=2048, 32nt x 4sp x 16ch ----
            if (blk < 128) {
                int nt = blk >> 2, sp = blk & 3;
                tc_gemm(g_cat2, K2A, g_W2 + (size_t)(nt*128)*K2A, K2A,
                        g_pz[sp] + nt*128, NG, sp*512, 16, smb);
            }
            grid_sync(gen);

            // ---- P6b: gates 2 epilogue ----
            for (int i = blk*256 + tid; i < BH/4; i += NB*256) {
                int m = i >> 8, c4 = (i & 255) * 4;
                float4 z[4];
                #pragma unroll
                for (int g = 0; g < 4; ++g) {
                    int col = g*HH + c4;
                    float4 sum = *(const float4*)(b2 + col);
                    #pragma unroll
                    for (int s = 0; s < 4; ++s) {
                        float4 p = *(const float4*)(g_pz[s] + (size_t)m*NG + col);
                        sum.x += p.x; sum.y += p.y; sum.z += p.z; sum.w += p.w;
                    }
                    z[g] = sum;
                }
                size_t idx = (size_t)m*HH + c4;
                float4 co = *(const float4*)(g_c2 + idx);
                float cn0 = sigm(z[1].x)*co.x + sigm(z[0].x)*tanhf(z[2].x);
                float cn1 = sigm(z[1].y)*co.y + sigm(z[0].y)*tanhf(z[2].y);
                float cn2 = sigm(z[1].z)*co.z + sigm(z[0].z)*tanhf(z[2].z);
                float cn3 = sigm(z[1].w)*co.w + sigm(z[0].w)*tanhf(z[2].w);
                float hn0 = sigm(z[3].x)*tanhf(cn0);
                float hn1 = sigm(z[3].y)*tanhf(cn1);
                float hn2 = sigm(z[3].z)*tanhf(cn2);
                float hn3 = sigm(z[3].w)*tanhf(cn3);
                *(float4*)(g_c2 + idx) = make_float4(cn0, cn1, cn2, cn3);
                *(float4*)(g_h2 + idx) = make_float4(hn0, hn1, hn2, hn3);
                *(float4*)(out + ((size_t)m*SS + t)*HH + c4) = make_float4(hn0, hn1, hn2, hn3);
            }
            grid_sync(gen);
        }
    }

    size_t off1 = (size_t)BB*SS*HH;
    for (int i = blk*256 + tid; i < BH; i += NB*256) {
        out[off1 + i]      = g_h2[i];
        out[off1 + BH + i] = g_c2[i];
    }
}

extern "C" void kernel_launch(void* const* d_in, const int* in_sizes, int n_in,
                              void* d_out, int out_size)
{
    const int*   enc  = (const int*)d_in[0];
    const int*   encx = (const int*)d_in[1];
    const float* wemb = (const float*)d_in[2];
    const float* xemb = (const float*)d_in[3];
    const float* Wsi  = (const float*)d_in[4];
    const float* Wsh  = (const float*)d_in[5];
    const float* b_bd = (const float*)d_in[6];
    const float* vs   = (const float*)d_in[7];
    const float* Wmx1 = (const float*)d_in[8];
    const float* Wmh1 = (const float*)d_in[9];
    const float* Wih1 = (const float*)d_in[10];
    const float* Whh1 = (const float*)d_in[11];
    const float* b1   = (const float*)d_in[12];
    const float* Wmx2 = (const float*)d_in[13];
    const float* Wmh2 = (const float*)d_in[14];
    const float* Wih2 = (const float*)d_in[15];
    const float* Whh2 = (const float*)d_in[16];
    const float* b2   = (const float*)d_in[17];
    float* out = (float*)d_out;
    size_t off1 = (size_t)BB*SS*HH;
    float* flags_ptr = out + off1 + 2*(size_t)BH;

    static int smem_set = 0;
    if (!smem_set) {
        cudaFuncSetAttribute(main_kernel, cudaFuncAttributeMaxDynamicSharedMemorySize,
                             SMEM_DYN);
        smem_set = 1;
    }

    prep_kernel  <<<7, 256>>>(Wsi, Wsh, b_bd, vs);
    prep2_kernel <<<4096, 256>>>(Wih1, Whh1, Wih2, Whh2);
    zero_kernel  <<<512, 256>>>();
    gather_kernel<<<2048, 256>>>(enc, encx, wemb, xemb);
    main_kernel  <<<NB, 256, SMEM_DYN>>>(Wmx1, Wmh1, b1, Wmx2, Wmh2, b2,
                                         out, flags_ptr);
}